// round 12
// baseline (speedup 1.0000x reference)
#include <cuda_runtime.h>
#include <cuda_bf16.h>
#include <mma.h>
#include <cstdint>

using namespace nvcuda;

#define T_STEPS 512
#define BATCH   64
#define DIN     1024
#define HID     1024
#define N3      3072   // [z | r | c] precomputed x-projections
#define MROWS   (T_STEPS * BATCH)   // 32768

// ---------------- static device scratch (no runtime allocation) ----------------
__device__ float g_P[(size_t)MROWS * N3];               // 384 MB: x-projections (fp32)
__device__ __nv_bfloat16 g_Xh[(size_t)MROWS * DIN];     // X hi (bf16)
__device__ __nv_bfloat16 g_Xl[(size_t)MROWS * DIN];     // X lo
__device__ __nv_bfloat16 g_Bh[(size_t)N3 * DIN];        // phase-1 W rows [n][k] hi
__device__ __nv_bfloat16 g_Bl[(size_t)N3 * DIN];        // phase-1 W rows [n][k] lo
__device__ __nv_bfloat16 g_WAh[2048 * 1024];            // Wfc h-part rows [n][k] hi
__device__ __nv_bfloat16 g_WAl[2048 * 1024];            // lo
__device__ __nv_bfloat16 g_WBh[1024 * 1024];            // Wfc2 h-part rows [n][k] hi
__device__ __nv_bfloat16 g_WBl[1024 * 1024];            // lo
__device__ float g_hb[BATCH * HID];                     // h fp32 (carried state)
__device__ __nv_bfloat16 g_hbh[BATCH * HID];            // h hi
__device__ __nv_bfloat16 g_hbl[BATCH * HID];            // h lo
__device__ float g_z[BATCH * HID];                      // z gate (fp32)
__device__ __nv_bfloat16 g_rhh[BATCH * HID];            // r*h hi
__device__ __nv_bfloat16 g_rhl[BATCH * HID];            // r*h lo
__device__ unsigned g_cR, g_cZ, g_cB;                   // role counters

// ---------------- init ----------------
__global__ void init_kernel() {
    int i = blockIdx.x * blockDim.x + threadIdx.x;
    if (i == 0) { g_cR = 0u; g_cZ = 0u; g_cB = 0u; }
    if (i < HID * BATCH) {
        float h0 = 1e-9f;
        g_hb[i] = h0;
        __nv_bfloat16 hh = __float2bfloat16(h0);
        g_hbh[i] = hh;
        g_hbl[i] = __float2bfloat16(h0 - __bfloat162float(hh));
    }
}

// ---------------- convert: fp32 -> bf16 hi/lo for X and all weight views ----------------
__global__ void convert_kernel(const float* __restrict__ x,
                               const float* __restrict__ Wfc,
                               const float* __restrict__ Wfc2) {
    int i = blockIdx.x * blockDim.x + threadIdx.x;
    const size_t NX = (size_t)MROWS * DIN;
    if ((size_t)i < NX) {
        float a = x[i];
        __nv_bfloat16 h = __float2bfloat16(a);
        g_Xh[i] = h;
        g_Xl[i] = __float2bfloat16(a - __bfloat162float(h));
    }
    if (i < N3 * DIN) {            // phase-1 weights: x-part rows
        int n = i >> 10, k = i & 1023;
        float a = (n < 2048) ? Wfc[(size_t)n * 2048 + k]
                             : Wfc2[(size_t)(n - 2048) * 2048 + k];
        __nv_bfloat16 h = __float2bfloat16(a);
        g_Bh[i] = h;
        g_Bl[i] = __float2bfloat16(a - __bfloat162float(h));
    }
    if (i < 2048 * 1024) {         // Wfc h-part rows
        int n = i >> 10, k = i & 1023;
        float a = Wfc[(size_t)n * 2048 + 1024 + k];
        __nv_bfloat16 h = __float2bfloat16(a);
        g_WAh[i] = h;
        g_WAl[i] = __float2bfloat16(a - __bfloat162float(h));
    }
    if (i < 1024 * 1024) {         // Wfc2 h-part rows
        int n = i >> 10, k = i & 1023;
        float a = Wfc2[(size_t)n * 2048 + 1024 + k];
        __nv_bfloat16 h = __float2bfloat16(a);
        g_WBh[i] = h;
        g_WBl[i] = __float2bfloat16(a - __bfloat162float(h));
    }
}

// ---------------- phase 1 (WMMA bf16 hi/lo split, reg double-buffer): P = X @ W^T ----------------
#define LDT 40

__global__ void __launch_bounds__(256) gemm_p_wmma_kernel() {
    __shared__ __nv_bfloat16 Ah[128][LDT];
    __shared__ __nv_bfloat16 Al[128][LDT];
    __shared__ __nv_bfloat16 Bh[128][LDT];
    __shared__ __nv_bfloat16 Bl[128][LDT];

    const int tid = threadIdx.x, wid = tid >> 5;
    const int m0 = (blockIdx.x / 24) << 7;
    const int n0 = (blockIdx.x % 24) << 7;
    const int wm = (wid >> 2) << 6;
    const int wn = (wid & 3) << 5;

    wmma::fragment<wmma::accumulator, 16, 16, 16, float> acc[4][2];
#pragma unroll
    for (int i = 0; i < 4; i++)
#pragma unroll
        for (int j = 0; j < 2; j++) wmma::fill_fragment(acc[i][j], 0.0f);

#pragma unroll
    for (int i = tid; i < 512; i += 256) {
        int r = i >> 2, c = (i & 3) << 3;
        *(uint4*)&Ah[r][c] = *(const uint4*)(g_Xh + (size_t)(m0 + r) * DIN + c);
        *(uint4*)&Al[r][c] = *(const uint4*)(g_Xl + (size_t)(m0 + r) * DIN + c);
        *(uint4*)&Bh[r][c] = *(const uint4*)(g_Bh + (size_t)(n0 + r) * DIN + c);
        *(uint4*)&Bl[r][c] = *(const uint4*)(g_Bl + (size_t)(n0 + r) * DIN + c);
    }
    __syncthreads();

    for (int k0 = 0; k0 < DIN; k0 += 32) {
        const bool nxt = (k0 + 32) < DIN;
        uint4 pxh[2], pxl[2], pwh[2], pwl[2];
        if (nxt) {
#pragma unroll
            for (int ii = 0; ii < 2; ii++) {
                int i = tid + (ii << 8);
                int r = i >> 2, c = (i & 3) << 3;
                pxh[ii] = *(const uint4*)(g_Xh + (size_t)(m0 + r) * DIN + k0 + 32 + c);
                pxl[ii] = *(const uint4*)(g_Xl + (size_t)(m0 + r) * DIN + k0 + 32 + c);
                pwh[ii] = *(const uint4*)(g_Bh + (size_t)(n0 + r) * DIN + k0 + 32 + c);
                pwl[ii] = *(const uint4*)(g_Bl + (size_t)(n0 + r) * DIN + k0 + 32 + c);
            }
        }
#pragma unroll
        for (int kk = 0; kk < 32; kk += 16) {
            wmma::fragment<wmma::matrix_a, 16, 16, 16, __nv_bfloat16, wmma::row_major> fah[4], fal[4];
            wmma::fragment<wmma::matrix_b, 16, 16, 16, __nv_bfloat16, wmma::col_major> fbh[2], fbl[2];
#pragma unroll
            for (int i = 0; i < 4; i++) {
                wmma::load_matrix_sync(fah[i], &Ah[wm + i * 16][kk], LDT);
                wmma::load_matrix_sync(fal[i], &Al[wm + i * 16][kk], LDT);
            }
#pragma unroll
            for (int j = 0; j < 2; j++) {
                wmma::load_matrix_sync(fbh[j], &Bh[wn + j * 16][kk], LDT);
                wmma::load_matrix_sync(fbl[j], &Bl[wn + j * 16][kk], LDT);
            }
#pragma unroll
            for (int i = 0; i < 4; i++)
#pragma unroll
                for (int j = 0; j < 2; j++) {
                    wmma::mma_sync(acc[i][j], fah[i], fbh[j], acc[i][j]);
                    wmma::mma_sync(acc[i][j], fah[i], fbl[j], acc[i][j]);
                    wmma::mma_sync(acc[i][j], fal[i], fbh[j], acc[i][j]);
                }
        }
        __syncthreads();
        if (nxt) {
#pragma unroll
            for (int ii = 0; ii < 2; ii++) {
                int i = tid + (ii << 8);
                int r = i >> 2, c = (i & 3) << 3;
                *(uint4*)&Ah[r][c] = pxh[ii];
                *(uint4*)&Al[r][c] = pxl[ii];
                *(uint4*)&Bh[r][c] = pwh[ii];
                *(uint4*)&Bl[r][c] = pwl[ii];
            }
            __syncthreads();
        }
    }
#pragma unroll
    for (int i = 0; i < 4; i++)
#pragma unroll
        for (int j = 0; j < 2; j++)
            wmma::store_matrix_sync(
                g_P + (size_t)(m0 + wm + i * 16) * N3 + n0 + wn + j * 16,
                acc[i][j], N3, wmma::mem_row_major);
}

// ---------------- counter sync primitives (release/acquire, no L1 flush) ----------------
__device__ __forceinline__ void ctr_arrive(unsigned* ctr) {
    __syncthreads();   // all block stores happen-before tid0's release
    if (threadIdx.x == 0)
        asm volatile("red.release.gpu.add.u32 [%0], %1;" :: "l"(ctr), "r"(1u) : "memory");
}
__device__ __forceinline__ void ctr_wait(unsigned* ctr, unsigned target) {
    if (threadIdx.x == 0) {
        unsigned v;
        do {
            asm volatile("ld.acquire.gpu.u32 %0, [%1];" : "=r"(v) : "l"(ctr) : "memory");
        } while (v < target);
    }
    __syncthreads();   // broadcast acquire to whole block
}

// ---------------- persistent sequential kernel: role-specialized, full-K resident ----------------
// 96 blocks x 512 threads:
//   blocks  0..31 : z-GEMM   (cols n0=bid*32 of [z], K=1024)      -> g_z
//   blocks 32..63 : r-GEMM   (cols n0=bid*32 of [z|r], K=1024)    -> g_rhh/g_rhl
//   blocks 64..95 : c-GEMM   (cols m0=(bid-64)*32, K=1024)        -> h update + out
// Weights (32 rows x 1024 k, bf16 hi/lo = 129 KB) resident in smem per block.
// A-operand (h or r*h, 64x1024 hi/lo = 256 KB) streamed in 8 chunks of 128k,
// double-buffered; 16 warps = 8 output frags x 2-way K-split, reduced in smem.
#define NBLK    96
#define WPITCH  1032
#define HPITCH  136
#define SPITCH  36
#define SEQ_SMEM_BYTES (2*32*WPITCH*2 + 2*2*64*HPITCH*2)   // 132096 + 69632 = 201728

__global__ void __launch_bounds__(512, 1) seq_kernel(float* __restrict__ out) {
    extern __shared__ char smem_raw[];
    __nv_bfloat16* sWh = (__nv_bfloat16*)smem_raw;          // [32][1032]
    __nv_bfloat16* sWl = sWh + 32 * WPITCH;                 // [32][1032]
    __nv_bfloat16* sH  = sWl + 32 * WPITCH;                 // [2 buf][2 hl][64][136]
    float* scratch = (float*)sH;                            // [2 kq][64][36] (aliased)

    const int tid = threadIdx.x, bid = blockIdx.x;
    const int wid = tid >> 5;
    const bool isA = bid < 64;
    const bool isR = (bid >= 32) && isA;
    const int n0 = isA ? bid * 32 : (bid - 64) * 32;  // A: [0,2048); B: [0,1024)
    const int fr = wid & 3, fc = (wid >> 2) & 1, kq = wid >> 3;

    // ---- one-time weight preload (32 rows x 1024 k, hi/lo) ----
    {
        const __nv_bfloat16* gWh = isA ? g_WAh : g_WBh;
        const __nv_bfloat16* gWl = isA ? g_WAl : g_WBl;
        for (int u = tid; u < 4096; u += 512) {
            int r = u >> 7, c8 = (u & 127) << 3;
            *(uint4*)&sWh[r * WPITCH + c8] = *(const uint4*)(gWh + (size_t)(n0 + r) * 1024 + c8);
            *(uint4*)&sWl[r * WPITCH + c8] = *(const uint4*)(gWl + (size_t)(n0 + r) * 1024 + c8);
        }
        __syncthreads();
    }

    const __nv_bfloat16* gSh = isA ? g_hbh : g_rhh;
    const __nv_bfloat16* gSl = isA ? g_hbl : g_rhl;
    const int srow = tid >> 4, sq = (tid & 15) << 3;   // stream loader coords (x2 passes)
    const int srow2 = srow + 32;

    for (int t = 0; t < T_STEPS; t++) {
        // ---- dependency waits ----
        if (isA) { if (t) ctr_wait(&g_cB, 32u * t); }     // h(t-1) ready
        else     { ctr_wait(&g_cR, 32u * (t + 1)); }      // r*h(t) ready

        // ---- chunk 0 direct load ----
#pragma unroll
        for (int p = 0; p < 2; p++) {
            const __nv_bfloat16* src = p ? gSl : gSh;
            __nv_bfloat16* dst = sH + (size_t)p * (64 * HPITCH);
            *(uint4*)&dst[srow  * HPITCH + sq] = __ldcg((const uint4*)(src + srow  * 1024 + sq));
            *(uint4*)&dst[srow2 * HPITCH + sq] = __ldcg((const uint4*)(src + srow2 * 1024 + sq));
        }
        __syncthreads();

        wmma::fragment<wmma::accumulator, 16, 16, 16, float> acc;
        wmma::fill_fragment(acc, 0.0f);

        for (int c = 0; c < 8; c++) {
            uint4 pre[4];
            if (c < 7) {
                int c0 = (c + 1) << 7;
#pragma unroll
                for (int p = 0; p < 2; p++) {
                    const __nv_bfloat16* src = p ? gSl : gSh;
                    pre[p * 2 + 0] = __ldcg((const uint4*)(src + srow  * 1024 + c0 + sq));
                    pre[p * 2 + 1] = __ldcg((const uint4*)(src + srow2 * 1024 + c0 + sq));
                }
            }
            if (kq == (c >> 2)) {
                const __nv_bfloat16* bufH = sH + (size_t)(c & 1) * (2 * 64 * HPITCH);
                const __nv_bfloat16* bufL = bufH + 64 * HPITCH;
                const int kw = c << 7;
#pragma unroll
                for (int kk = 0; kk < 128; kk += 16) {
                    wmma::fragment<wmma::matrix_a, 16, 16, 16, __nv_bfloat16, wmma::row_major> fah, fal;
                    wmma::fragment<wmma::matrix_b, 16, 16, 16, __nv_bfloat16, wmma::col_major> fbh, fbl;
                    wmma::load_matrix_sync(fah, bufH + (fr * 16) * HPITCH + kk, HPITCH);
                    wmma::load_matrix_sync(fal, bufL + (fr * 16) * HPITCH + kk, HPITCH);
                    wmma::load_matrix_sync(fbh, sWh + (fc * 16) * WPITCH + kw + kk, WPITCH);
                    wmma::load_matrix_sync(fbl, sWl + (fc * 16) * WPITCH + kw + kk, WPITCH);
                    wmma::mma_sync(acc, fah, fbh, acc);
                    wmma::mma_sync(acc, fah, fbl, acc);
                    wmma::mma_sync(acc, fal, fbh, acc);
                }
            }
            __syncthreads();
            if (c < 7) {
                __nv_bfloat16* dst0 = sH + (size_t)((c + 1) & 1) * (2 * 64 * HPITCH);
#pragma unroll
                for (int p = 0; p < 2; p++) {
                    __nv_bfloat16* dst = dst0 + (size_t)p * (64 * HPITCH);
                    *(uint4*)&dst[srow  * HPITCH + sq] = pre[p * 2 + 0];
                    *(uint4*)&dst[srow2 * HPITCH + sq] = pre[p * 2 + 1];
                }
                __syncthreads();
            }
        }

        // ---- K-split reduce (2-way) via smem scratch (aliased onto stream bufs) ----
        wmma::store_matrix_sync(scratch + (kq * 64 + fr * 16) * SPITCH + fc * 16,
                                acc, SPITCH, wmma::mem_row_major);
        __syncthreads();

        // ---- epilogue: 2048 outputs, 4 per thread (float4) ----
        {
            const int e = tid << 2;
            const int b = e >> 5, j = e & 31;
            float4 s0 = *(float4*)&scratch[(b) * SPITCH + j];
            float4 s1 = *(float4*)&scratch[(64 + b) * SPITCH + j];
            const int pcol = isA ? n0 : (2048 + n0);
            float4 px = __ldcg((const float4*)(g_P + (size_t)t * (BATCH * N3) + b * N3 + pcol + j));
            float sx = s0.x + s1.x + px.x, sy = s0.y + s1.y + px.y;
            float sz = s0.z + s1.z + px.z, sw = s0.w + s1.w + px.w;

            if (isA) {
                float4 g;
                g.x = 1.0f / (1.0f + __expf(-sx));
                g.y = 1.0f / (1.0f + __expf(-sy));
                g.z = 1.0f / (1.0f + __expf(-sz));
                g.w = 1.0f / (1.0f + __expf(-sw));
                if (!isR) {
                    *(float4*)&g_z[b * 1024 + n0 + j] = g;
                } else {
                    const int k = n0 - 1024 + j;
                    float4 h = __ldcg((const float4*)&g_hb[b * 1024 + k]);
                    float r0 = g.x * h.x, r1 = g.y * h.y, r2 = g.z * h.z, r3 = g.w * h.w;
                    __align__(8) __nv_bfloat16 hh[4], hl[4];
                    hh[0] = __float2bfloat16(r0); hl[0] = __float2bfloat16(r0 - __bfloat162float(hh[0]));
                    hh[1] = __float2bfloat16(r1); hl[1] = __float2bfloat16(r1 - __bfloat162float(hh[1]));
                    hh[2] = __float2bfloat16(r2); hl[2] = __float2bfloat16(r2 - __bfloat162float(hh[2]));
                    hh[3] = __float2bfloat16(r3); hl[3] = __float2bfloat16(r3 - __bfloat162float(hh[3]));
                    *(uint2*)&g_rhh[b * 1024 + k] = *(uint2*)hh;
                    *(uint2*)&g_rhl[b * 1024 + k] = *(uint2*)hl;
                }
                ctr_arrive(isR ? &g_cR : &g_cZ);
            } else {
                float c0 = tanhf(sx), c1 = tanhf(sy), c2 = tanhf(sz), c3 = tanhf(sw);
                ctr_wait(&g_cZ, 32u * (t + 1));           // z(t) ready (also guards h anti-dep)
                const int o = b * 1024 + n0 + j;
                float4 zv = __ldcg((const float4*)&g_z[o]);
                float4 h  = __ldcg((const float4*)&g_hb[o]);
                float h0 = fmaf(zv.x, c0 - h.x, h.x);
                float h1 = fmaf(zv.y, c1 - h.y, h.y);
                float h2 = fmaf(zv.z, c2 - h.z, h.z);
                float h3 = fmaf(zv.w, c3 - h.w, h.w);
                *(float4*)&out[(size_t)t * (BATCH * HID) + o] = make_float4(h0, h1, h2, h3);
                *(float4*)&g_hb[o] = make_float4(h0, h1, h2, h3);
                __align__(8) __nv_bfloat16 hh[4], hl[4];
                hh[0] = __float2bfloat16(h0); hl[0] = __float2bfloat16(h0 - __bfloat162float(hh[0]));
                hh[1] = __float2bfloat16(h1); hl[1] = __float2bfloat16(h1 - __bfloat162float(hh[1]));
                hh[2] = __float2bfloat16(h2); hl[2] = __float2bfloat16(h2 - __bfloat162float(hh[2]));
                hh[3] = __float2bfloat16(h3); hl[3] = __float2bfloat16(h3 - __bfloat162float(hh[3]));
                *(uint2*)&g_hbh[o] = *(uint2*)hh;
                *(uint2*)&g_hbl[o] = *(uint2*)hl;
                ctr_arrive(&g_cB);
            }
        }
        __syncthreads();   // protect scratch/bufs before next step's chunk-0 store
    }
}

// ---------------- launch (4 graph nodes total) ----------------
extern "C" void kernel_launch(void* const* d_in, const int* in_sizes, int n_in,
                              void* d_out, int out_size) {
    const float* x    = (const float*)d_in[0];   // [512, 64, 1024]
    const float* Wfc  = (const float*)d_in[1];   // [2048, 2048]
    const float* Wfc2 = (const float*)d_in[2];   // [1024, 2048]
    // d_in[3] (w_hh), d_in[4] (bias): dead — delta_u never reaches the output
    float* out = (float*)d_out;                  // [512, 64, 1024]

    // One-time dynamic-smem opt-in; never executed during graph capture
    // (first kernel_launch call is the uncaptured correctness run).
    static bool attr_done = false;
    if (!attr_done) {
        cudaFuncSetAttribute(seq_kernel,
                             cudaFuncAttributeMaxDynamicSharedMemorySize, SEQ_SMEM_BYTES);
        attr_done = true;
    }

    init_kernel<<<256, 256>>>();
    convert_kernel<<<(MROWS * DIN + 255) / 256, 256>>>(x, Wfc, Wfc2);
    gemm_p_wmma_kernel<<<(MROWS / 128) * (N3 / 128), 256>>>();
    seq_kernel<<<NBLK, 512, SEQ_SMEM_BYTES>>>(out);
}

// round 13
// speedup vs baseline: 1.5199x; 1.5199x over previous
#include <cuda_runtime.h>
#include <cuda_bf16.h>
#include <mma.h>
#include <cstdint>

using namespace nvcuda;

#define T_STEPS 512
#define BATCH   64
#define DIN     1024
#define HID     1024
#define N3      3072   // [z | r | c] precomputed x-projections
#define MROWS   (T_STEPS * BATCH)   // 32768

// ---------------- static device scratch (no runtime allocation) ----------------
__device__ float g_P[(size_t)MROWS * N3];               // 384 MB: x-projections (fp32)
__device__ __nv_bfloat16 g_Xh[(size_t)MROWS * DIN];     // X hi (bf16)
__device__ __nv_bfloat16 g_Xl[(size_t)MROWS * DIN];     // X lo
__device__ __nv_bfloat16 g_Bh[(size_t)N3 * DIN];        // phase-1 W rows [n][k] hi
__device__ __nv_bfloat16 g_Bl[(size_t)N3 * DIN];        // phase-1 W rows [n][k] lo
__device__ __nv_bfloat16 g_WAh[2048 * 1024];            // Wfc h-part rows [n][k] hi
__device__ __nv_bfloat16 g_WAl[2048 * 1024];            // lo
__device__ __nv_bfloat16 g_WBh[1024 * 1024];            // Wfc2 h-part rows [n][k] hi
__device__ __nv_bfloat16 g_WBl[1024 * 1024];            // lo
__device__ float g_hb[BATCH * HID];                     // h fp32 (carried state)
__device__ __nv_bfloat16 g_hbh[BATCH * HID];            // h hi
__device__ __nv_bfloat16 g_hbl[BATCH * HID];            // h lo
__device__ float g_PA[4 * BATCH * 2048];                // split-K partials stage A (2MB)
__device__ float g_PB[16 * BATCH * HID];                // split-K partials stage B (4MB)
__device__ unsigned g_bar;                              // grid barrier counter

// ---------------- init ----------------
__global__ void init_kernel() {
    int i = blockIdx.x * blockDim.x + threadIdx.x;
    if (i == 0) g_bar = 0u;
    if (i < HID * BATCH) {
        float h0 = 1e-9f;
        g_hb[i] = h0;
        __nv_bfloat16 hh = __float2bfloat16(h0);
        g_hbh[i] = hh;
        g_hbl[i] = __float2bfloat16(h0 - __bfloat162float(hh));
    }
}

// ---------------- convert: fp32 -> bf16 hi/lo for X and all weight views ----------------
__global__ void convert_kernel(const float* __restrict__ x,
                               const float* __restrict__ Wfc,
                               const float* __restrict__ Wfc2) {
    int i = blockIdx.x * blockDim.x + threadIdx.x;
    const size_t NX = (size_t)MROWS * DIN;
    if ((size_t)i < NX) {
        float a = x[i];
        __nv_bfloat16 h = __float2bfloat16(a);
        g_Xh[i] = h;
        g_Xl[i] = __float2bfloat16(a - __bfloat162float(h));
    }
    if (i < N3 * DIN) {            // phase-1 weights: x-part rows
        int n = i >> 10, k = i & 1023;
        float a = (n < 2048) ? Wfc[(size_t)n * 2048 + k]
                             : Wfc2[(size_t)(n - 2048) * 2048 + k];
        __nv_bfloat16 h = __float2bfloat16(a);
        g_Bh[i] = h;
        g_Bl[i] = __float2bfloat16(a - __bfloat162float(h));
    }
    if (i < 2048 * 1024) {         // Wfc h-part rows
        int n = i >> 10, k = i & 1023;
        float a = Wfc[(size_t)n * 2048 + 1024 + k];
        __nv_bfloat16 h = __float2bfloat16(a);
        g_WAh[i] = h;
        g_WAl[i] = __float2bfloat16(a - __bfloat162float(h));
    }
    if (i < 1024 * 1024) {         // Wfc2 h-part rows
        int n = i >> 10, k = i & 1023;
        float a = Wfc2[(size_t)n * 2048 + 1024 + k];
        __nv_bfloat16 h = __float2bfloat16(a);
        g_WBh[i] = h;
        g_WBl[i] = __float2bfloat16(a - __bfloat162float(h));
    }
}

// ---------------- phase 1 (WMMA bf16 hi/lo split): P = X @ W^T ----------------
// 128x128 block tile, 512 threads (16 warps, 32x32 warp tiles) for 2x occupancy.
#define LDT 40

__global__ void __launch_bounds__(512) gemm_p_wmma_kernel() {
    __shared__ __nv_bfloat16 Ah[128][LDT];
    __shared__ __nv_bfloat16 Al[128][LDT];
    __shared__ __nv_bfloat16 Bh[128][LDT];
    __shared__ __nv_bfloat16 Bl[128][LDT];

    const int tid = threadIdx.x, wid = tid >> 5;
    const int m0 = (blockIdx.x / 24) << 7;
    const int n0 = (blockIdx.x % 24) << 7;
    const int wm = (wid >> 2) << 5;   // 0,32,64,96
    const int wn = (wid & 3) << 5;    // 0,32,64,96
    const int lr = tid >> 2, lc = (tid & 3) << 3;   // loader: 1 uint4 per tile

    wmma::fragment<wmma::accumulator, 16, 16, 16, float> acc[2][2];
#pragma unroll
    for (int i = 0; i < 2; i++)
#pragma unroll
        for (int j = 0; j < 2; j++) wmma::fill_fragment(acc[i][j], 0.0f);

    *(uint4*)&Ah[lr][lc] = *(const uint4*)(g_Xh + (size_t)(m0 + lr) * DIN + lc);
    *(uint4*)&Al[lr][lc] = *(const uint4*)(g_Xl + (size_t)(m0 + lr) * DIN + lc);
    *(uint4*)&Bh[lr][lc] = *(const uint4*)(g_Bh + (size_t)(n0 + lr) * DIN + lc);
    *(uint4*)&Bl[lr][lc] = *(const uint4*)(g_Bl + (size_t)(n0 + lr) * DIN + lc);
    __syncthreads();

    for (int k0 = 0; k0 < DIN; k0 += 32) {
        const bool nxt = (k0 + 32) < DIN;
        uint4 pxh, pxl, pwh, pwl;
        if (nxt) {
            pxh = *(const uint4*)(g_Xh + (size_t)(m0 + lr) * DIN + k0 + 32 + lc);
            pxl = *(const uint4*)(g_Xl + (size_t)(m0 + lr) * DIN + k0 + 32 + lc);
            pwh = *(const uint4*)(g_Bh + (size_t)(n0 + lr) * DIN + k0 + 32 + lc);
            pwl = *(const uint4*)(g_Bl + (size_t)(n0 + lr) * DIN + k0 + 32 + lc);
        }
#pragma unroll
        for (int kk = 0; kk < 32; kk += 16) {
            wmma::fragment<wmma::matrix_a, 16, 16, 16, __nv_bfloat16, wmma::row_major> fah[2], fal[2];
            wmma::fragment<wmma::matrix_b, 16, 16, 16, __nv_bfloat16, wmma::col_major> fbh[2], fbl[2];
#pragma unroll
            for (int i = 0; i < 2; i++) {
                wmma::load_matrix_sync(fah[i], &Ah[wm + i * 16][kk], LDT);
                wmma::load_matrix_sync(fal[i], &Al[wm + i * 16][kk], LDT);
            }
#pragma unroll
            for (int j = 0; j < 2; j++) {
                wmma::load_matrix_sync(fbh[j], &Bh[wn + j * 16][kk], LDT);
                wmma::load_matrix_sync(fbl[j], &Bl[wn + j * 16][kk], LDT);
            }
#pragma unroll
            for (int i = 0; i < 2; i++)
#pragma unroll
                for (int j = 0; j < 2; j++) {
                    wmma::mma_sync(acc[i][j], fah[i], fbh[j], acc[i][j]);
                    wmma::mma_sync(acc[i][j], fah[i], fbl[j], acc[i][j]);
                    wmma::mma_sync(acc[i][j], fal[i], fbh[j], acc[i][j]);
                }
        }
        __syncthreads();
        if (nxt) {
            *(uint4*)&Ah[lr][lc] = pxh;
            *(uint4*)&Al[lr][lc] = pxl;
            *(uint4*)&Bh[lr][lc] = pwh;
            *(uint4*)&Bl[lr][lc] = pwl;
            __syncthreads();
        }
    }
#pragma unroll
    for (int i = 0; i < 2; i++)
#pragma unroll
        for (int j = 0; j < 2; j++)
            wmma::store_matrix_sync(
                g_P + (size_t)(m0 + wm + i * 16) * N3 + n0 + wn + j * 16,
                acc[i][j], N3, wmma::mem_row_major);
}

// ---------------- grid barrier: CG-style release/acquire (no L1 flush) ----------------
__device__ __forceinline__ void grid_bar(unsigned target) {
    __syncthreads();
    if (threadIdx.x == 0) {
        unsigned* bar = &g_bar;
        asm volatile("red.release.gpu.add.u32 [%0], %1;" :: "l"(bar), "r"(1u) : "memory");
        unsigned v;
        do {
            asm volatile("ld.acquire.gpu.u32 %0, [%1];" : "=r"(v) : "l"(bar) : "memory");
        } while (v < target);
    }
    __syncthreads();
}

// ---------------- persistent sequential kernel: weights resident, rebalanced split-K ----------------
// 128 blocks x 512 threads.
// Stage A: 4 kcA x 32 ctA units; out 64x64 @K=256; PA partials = 4.
// Stage B: 16 kcB x 8 ctB units; out 64x128 @K=64; PB partials = 16.
// smem: sWAh/l [64][264], sWBh/l [128][72], sHh/l [64][264]  = 172,032 B.
#define WA_PITCH 264
#define WB_PITCH 72
#define SEQ_SMEM_BYTES (2*64*WA_PITCH*2 + 2*128*WB_PITCH*2 + 2*64*WA_PITCH*2)
#define NBLK 128

__global__ void __launch_bounds__(512, 1) seq_kernel(float* __restrict__ out) {
    extern __shared__ __nv_bfloat16 smem[];
    __nv_bfloat16* sWAh = smem;
    __nv_bfloat16* sWAl = sWAh + 64 * WA_PITCH;
    __nv_bfloat16* sWBh = sWAl + 64 * WA_PITCH;
    __nv_bfloat16* sWBl = sWBh + 128 * WB_PITCH;
    __nv_bfloat16* sHh  = sWBl + 128 * WB_PITCH;
    __nv_bfloat16* sHl  = sHh  + 64 * WA_PITCH;

    const int tid = threadIdx.x, bid = blockIdx.x;
    const int wid = tid >> 5;
    const int gtid = bid * 512 + tid;          // 0..65535 == BATCH*HID
    const int wm  = (wid >> 2) << 4;   // rows: 0,16,32,48
    const int wnA = (wid & 3) << 4;    // stage-A cols: 0,16,32,48
    const int wnB = (wid & 3) << 5;    // stage-B cols: 0,32,64,96
    unsigned bar_t = 0;

    const int kcA = bid >> 5, ctA = bid & 31;      // stage-A unit
    const int k0A = kcA << 8, n0A = ctA << 6;
    const int kcB = bid >> 3, ctB = bid & 7;       // stage-B unit
    const int ks0B = kcB << 6, n0B = ctB << 7;

    // ---- one-time weight preload ----
    for (int u = tid; u < 2048; u += 512) {        // WA: 64 rows x 256 k, hi/lo
        int r = u >> 5, c8 = (u & 31) << 3;
        *(uint4*)&sWAh[r * WA_PITCH + c8] =
            *(const uint4*)(g_WAh + (size_t)(n0A + r) * 1024 + k0A + c8);
        *(uint4*)&sWAl[r * WA_PITCH + c8] =
            *(const uint4*)(g_WAl + (size_t)(n0A + r) * 1024 + k0A + c8);
    }
    for (int u = tid; u < 1024; u += 512) {        // WB: 128 rows x 64 k, hi/lo
        int r = u >> 3, c8 = (u & 7) << 3;
        *(uint4*)&sWBh[r * WB_PITCH + c8] =
            *(const uint4*)(g_WBh + (size_t)(n0B + r) * 1024 + ks0B + c8);
        *(uint4*)&sWBl[r * WB_PITCH + c8] =
            *(const uint4*)(g_WBl + (size_t)(n0B + r) * 1024 + ks0B + c8);
    }
    __syncthreads();

    for (int t = 0; t < T_STEPS; t++) {
        const float* Pt = g_P + (size_t)t * (BATCH * N3);

        // ======== stage A: PA[kcA] slice = h @ WA^T   (64x64 @K=256, weights resident)
        {
            for (int i = tid; i < 2048; i += 512) {    // h slice 64x256 hi/lo
                int r = i >> 5, c8 = (i & 31) << 3;
                *(uint4*)&sHh[r * WA_PITCH + c8] =
                    __ldcg((const uint4*)(g_hbh + (size_t)r * HID + k0A + c8));
                *(uint4*)&sHl[r * WA_PITCH + c8] =
                    __ldcg((const uint4*)(g_hbl + (size_t)r * HID + k0A + c8));
            }
            __syncthreads();

            wmma::fragment<wmma::accumulator, 16, 16, 16, float> acc;
            wmma::fill_fragment(acc, 0.0f);
#pragma unroll
            for (int kk = 0; kk < 256; kk += 16) {
                wmma::fragment<wmma::matrix_a, 16, 16, 16, __nv_bfloat16, wmma::row_major> fah, fal;
                wmma::fragment<wmma::matrix_b, 16, 16, 16, __nv_bfloat16, wmma::col_major> fbh, fbl;
                wmma::load_matrix_sync(fah, sHh + wm * WA_PITCH + kk, WA_PITCH);
                wmma::load_matrix_sync(fal, sHl + wm * WA_PITCH + kk, WA_PITCH);
                wmma::load_matrix_sync(fbh, sWAh + wnA * WA_PITCH + kk, WA_PITCH);
                wmma::load_matrix_sync(fbl, sWAl + wnA * WA_PITCH + kk, WA_PITCH);
                wmma::mma_sync(acc, fah, fbh, acc);
                wmma::mma_sync(acc, fah, fbl, acc);
                wmma::mma_sync(acc, fal, fbh, acc);
            }
            wmma::store_matrix_sync(
                g_PA + (size_t)kcA * (BATCH * 2048) + (size_t)wm * 2048 + n0A + wnA,
                acc, 2048, wmma::mem_row_major);
        }
        bar_t += NBLK; grid_bar(bar_t);

        // ======== stage B: fused r-reduce + (r*h) @ WB^T   (64x128 @K=64, weights resident)
        {
            for (int idx = tid; idx < 4096; idx += 512) {
                int kl = idx & 63, b = idx >> 6;
                int k = ks0B + kl;
                float s = Pt[b * N3 + 1024 + k];
#pragma unroll
                for (int c = 0; c < 4; c++)
                    s += __ldcg(&g_PA[c * (BATCH * 2048) + b * 2048 + 1024 + k]);
                float r = 1.0f / (1.0f + __expf(-s));
                float rh = r * __ldcg(&g_hb[(b << 10) + k]);
                __nv_bfloat16 hi = __float2bfloat16(rh);
                sHh[b * WA_PITCH + kl] = hi;
                sHl[b * WA_PITCH + kl] = __float2bfloat16(rh - __bfloat162float(hi));
            }
            __syncthreads();

            wmma::fragment<wmma::accumulator, 16, 16, 16, float> acc[2];
            wmma::fill_fragment(acc[0], 0.0f);
            wmma::fill_fragment(acc[1], 0.0f);
#pragma unroll
            for (int kk = 0; kk < 64; kk += 16) {
                wmma::fragment<wmma::matrix_a, 16, 16, 16, __nv_bfloat16, wmma::row_major> fah, fal;
                wmma::fragment<wmma::matrix_b, 16, 16, 16, __nv_bfloat16, wmma::col_major> fbh[2], fbl[2];
                wmma::load_matrix_sync(fah, sHh + wm * WA_PITCH + kk, WA_PITCH);
                wmma::load_matrix_sync(fal, sHl + wm * WA_PITCH + kk, WA_PITCH);
#pragma unroll
                for (int j = 0; j < 2; j++) {
                    wmma::load_matrix_sync(fbh[j], sWBh + (wnB + j * 16) * WB_PITCH + kk, WB_PITCH);
                    wmma::load_matrix_sync(fbl[j], sWBl + (wnB + j * 16) * WB_PITCH + kk, WB_PITCH);
                }
#pragma unroll
                for (int j = 0; j < 2; j++) {
                    wmma::mma_sync(acc[j], fah, fbh[j], acc[j]);
                    wmma::mma_sync(acc[j], fah, fbl[j], acc[j]);
                    wmma::mma_sync(acc[j], fal, fbh[j], acc[j]);
                }
            }
#pragma unroll
            for (int j = 0; j < 2; j++)
                wmma::store_matrix_sync(
                    g_PB + (size_t)kcB * (BATCH * 1024) + (size_t)wm * 1024 + n0B + wnB + j * 16,
                    acc[j], 1024, wmma::mem_row_major);
        }
        bar_t += NBLK; grid_bar(bar_t);

        // ======== stage C: z reduce + tanh(c) + blend + h update (+ bf16 mirror) + output
        {
            const int o = gtid;                 // one element per thread
            int b = o >> 10, j = o & 1023;
            float sz = Pt[b * N3 + j];
#pragma unroll
            for (int c = 0; c < 4; c++)
                sz += __ldcg(&g_PA[c * (BATCH * 2048) + b * 2048 + j]);
            float z = 1.0f / (1.0f + __expf(-sz));

            float sc = Pt[b * N3 + 2048 + j];
#pragma unroll
            for (int c = 0; c < 16; c++)
                sc += __ldcg(&g_PB[c * (BATCH * 1024) + o]);
            float cv = tanhf(sc);

            float hcur = __ldcg(&g_hb[o]);
            float hn = fmaf(z, cv - hcur, hcur);   // (1-z)*h + z*c
            out[(size_t)t * (BATCH * HID) + o] = hn;
            g_hb[o] = hn;
            __nv_bfloat16 hh = __float2bfloat16(hn);
            g_hbh[o] = hh;
            g_hbl[o] = __float2bfloat16(hn - __bfloat162float(hh));
        }
        bar_t += NBLK; grid_bar(bar_t);
    }
}

// ---------------- launch (4 graph nodes total) ----------------
extern "C" void kernel_launch(void* const* d_in, const int* in_sizes, int n_in,
                              void* d_out, int out_size) {
    const float* x    = (const float*)d_in[0];   // [512, 64, 1024]
    const float* Wfc  = (const float*)d_in[1];   // [2048, 2048]
    const float* Wfc2 = (const float*)d_in[2];   // [1024, 2048]
    // d_in[3] (w_hh), d_in[4] (bias): dead — delta_u never reaches the output
    float* out = (float*)d_out;                  // [512, 64, 1024]

    // One-time dynamic-smem opt-in; never executed during graph capture.
    static bool attr_done = false;
    if (!attr_done) {
        cudaFuncSetAttribute(seq_kernel,
                             cudaFuncAttributeMaxDynamicSharedMemorySize, SEQ_SMEM_BYTES);
        attr_done = true;
    }

    init_kernel<<<256, 256>>>();
    convert_kernel<<<(MROWS * DIN + 255) / 256, 256>>>(x, Wfc, Wfc2);
    gemm_p_wmma_kernel<<<(MROWS / 128) * (N3 / 128), 512>>>();
    seq_kernel<<<NBLK, 512, SEQ_SMEM_BYTES>>>(out);
}